// round 16
// baseline (speedup 1.0000x reference)
#include <cuda_runtime.h>
#include <cuda_fp16.h>
#include <cstdint>

#define TT    256
#define BATCH 4096
#define H1    16
#define H2    64

// ---------------------------------------------------------------------------
// Scratch
// ---------------------------------------------------------------------------
__device__ float g_out1[(size_t)TT * BATCH * H1];   // layer-1 outputs [T][B][16]
__device__ float g_h[2 * (size_t)BATCH * H2];       // final hidden per dir

// ---------------------------------------------------------------------------
// MUFU activations (EX2+RCP)
// ---------------------------------------------------------------------------
__device__ __forceinline__ float sig_mufu(float x) {
    return __fdividef(1.0f, 1.0f + __expf(-x));
}
__device__ __forceinline__ float tanh_mufu(float x) {
    return fmaf(2.0f, __fdividef(1.0f, 1.0f + __expf(-2.0f * x)), -1.0f);
}

__device__ __forceinline__ uint32_t smem_u32(const void* p) {
    uint32_t a;
    asm("{ .reg .u64 t; cvta.to.shared.u64 t, %1; cvt.u32.u64 %0, t; }" : "=r"(a) : "l"(p));
    return a;
}

#define LDSM_X4(r0, r1, r2, r3, addr) \
    asm volatile("ldmatrix.sync.aligned.m8n8.x4.shared.b16 {%0,%1,%2,%3}, [%4];" \
        : "=r"(r0), "=r"(r1), "=r"(r2), "=r"(r3) : "r"(addr))

#define MMA_F16(d, a0, a1, a2, a3, bb0, bb1) \
    asm volatile("mma.sync.aligned.m16n8k16.row.col.f32.f16.f16.f32 " \
        "{%0,%1,%2,%3}, {%4,%5,%6,%7}, {%8,%9}, {%0,%1,%2,%3};" \
        : "+f"((d)[0]), "+f"((d)[1]), "+f"((d)[2]), "+f"((d)[3]) \
        : "r"(a0), "r"(a1), "r"(a2), "r"(a3), "r"(bb0), "r"(bb1))

// fp16 split: v = hi + lo
__device__ __forceinline__ void f16_split(float v, unsigned short& hi, unsigned short& lo) {
    __half h = __float2half_rn(v);
    float rem = v - __half2float(h);
    __half l = __float2half_rn(rem);
    hi = __half_as_ushort(h);
    lo = __half_as_ushort(l);
}
__device__ __forceinline__ uint32_t f16_pair(float a, float b, uint32_t& lop) {
    unsigned short ha, la, hb, lb;
    f16_split(a, ha, la);
    f16_split(b, hb, lb);
    lop = (uint32_t)la | ((uint32_t)lb << 16);
    return (uint32_t)ha | ((uint32_t)hb << 16);
}

// ---------------------------------------------------------------------------
// Layer 2 (HMMA, fp16 3-term split), Whh_hi RESIDENT IN REGISTERS, rest of B
// from smem.  R15 analysis: B-in-regs halved the per-step time (hidden by a
// 1.73-ragged wave).  This round trades the once-used B parts back to smem
// (-72 regs) to reach 3 CTAs/SM (<=170 regs, 225.8 KB smem) -> 1.15 waves.
//   A: [0:64) h_hi | [64:128) h_lo | [128:144) x_hi | [144:160) x_lo
//   B: [0:64) Whh_hi | [64:128) Whh_lo | [128:144) Wih_hi | [144:160) Wih_lo
// CTA = 128 threads = 4 warps (warp jq owns gates [jq*16, +16)), M=16 rows.
// grid (256, 2) = 512 CTAs @ 3/SM.
// ---------------------------------------------------------------------------
#define AROW   336
#define SM_A0  0
#define SM_A1  5376                  // 16*336
#define SM_B   10752
#define SM2_TOTAL (10752 + 192 * 336)    // 75264 (x3 CTAs = 225792 <= 227KB)

__global__ void __launch_bounds__(128, 3)
gru2_kernel(const float* __restrict__ w_ihf, const float* __restrict__ w_hhf,
            const float* __restrict__ b_ihf, const float* __restrict__ b_hhf,
            const float* __restrict__ w_ihb, const float* __restrict__ w_hhb,
            const float* __restrict__ b_ihb, const float* __restrict__ b_hhb) {
    extern __shared__ char sm[];
    const uint32_t smb = smem_u32(sm);
    const int tid = threadIdx.x;
    const int wid = tid >> 5;
    const int lane = tid & 31;
    const int dir = blockIdx.y;
    const int b0 = blockIdx.x * 16;

    const float* w_ih = dir ? w_ihb : w_ihf;
    const float* w_hh = dir ? w_hhb : w_hhf;
    const float* b_ih = dir ? b_ihb : b_ihf;
    const float* b_hh = dir ? b_hhb : b_hhf;

    // ---- build B in smem ----
    for (int idx = tid; idx < 192 * 64; idx += 128) {
        int g = idx >> 6, k = idx & 63;
        unsigned short hi, lo;
        f16_split(w_hh[idx], hi, lo);
        unsigned short* row = (unsigned short*)(sm + SM_B + g * AROW);
        row[k] = hi; row[64 + k] = lo;
    }
    for (int idx = tid; idx < 192 * 16; idx += 128) {
        int g = idx >> 4, k = idx & 15;
        unsigned short hi, lo;
        f16_split(w_ih[idx], hi, lo);
        unsigned short* row = (unsigned short*)(sm + SM_B + g * AROW);
        row[128 + k] = hi; row[144 + k] = lo;
    }
    for (int g = tid; g < 192; g += 128)
        *(uint4*)(sm + SM_B + g * AROW + 320) = make_uint4(0, 0, 0, 0);

    // ---- zero A buf0 (h(0)=0) ----
    for (int idx = tid; idx < 16 * (AROW / 16); idx += 128)
        ((uint4*)(sm + SM_A0))[idx] = make_uint4(0, 0, 0, 0);
    __syncthreads();

    // ---- per-warp / per-lane constants ----
    const int jq = wid;                 // gate slice [jq*16, jq*16+16)
    const int lrow = lane & 7;
    const int grp  = lane >> 3;
    const uint32_t aRowOff = (uint32_t)(lrow + ((grp & 1) << 3)) * AROW
                           + (uint32_t)((grp >> 1) << 4);
    const uint32_t bOff = (uint32_t)(lrow + ((grp >> 1) << 3)) * AROW
                        + (uint32_t)((grp & 1) << 4);
    // per-section B row bases (for in-loop Whh_lo / Wih loads)
    const uint32_t rowS0 = smb + SM_B + bOff + (uint32_t)(jq * 16) * AROW;
    const uint32_t rowS1 = rowS0 + (uint32_t)64 * AROW;
    const uint32_t rowS2 = rowS0 + (uint32_t)128 * AROW;

    // ---- Whh_hi fragments resident in registers (used twice per step) ----
    uint32_t Bhh[3][4][4];
#pragma unroll
    for (int sec = 0; sec < 3; ++sec) {
        const uint32_t rowb = rowS0 + (uint32_t)(sec * 64) * AROW;
#pragma unroll
        for (int kc = 0; kc < 4; ++kc)
            LDSM_X4(Bhh[sec][kc][0], Bhh[sec][kc][1], Bhh[sec][kc][2], Bhh[sec][kc][3],
                    rowb + kc * 32);
    }

    // ---- stage x(t0): 128 threads = 16 rows x 8 col-pairs ----
    const int xrow = tid >> 3;          // 0..15
    const int xc2  = (tid & 7) * 2;     // 0,2,...,14
    {
        int t0 = dir ? (TT - 1) : 0;
        float2 xv = *(const float2*)(g_out1 + ((size_t)t0 * BATCH + b0 + xrow) * 16 + xc2);
        uint32_t LP, HP = f16_pair(xv.x, xv.y, LP);
        char* ar = sm + SM_A0 + xrow * AROW;
        *(uint32_t*)(ar + 256 + 2 * xc2) = HP;
        *(uint32_t*)(ar + 288 + 2 * xc2) = LP;
    }

    // biases (d-accumulator init values)
    const int cj = 2 * (lane & 3);
    float2 br[2], bz[2], bhn[2], bxn[2];
#pragma unroll
    for (int nbh = 0; nbh < 2; ++nbh) {
        int j = jq * 16 + nbh * 8 + cj;
        br[nbh]  = make_float2(b_ih[j] + b_hh[j],           b_ih[j + 1] + b_hh[j + 1]);
        bz[nbh]  = make_float2(b_ih[64 + j] + b_hh[64 + j], b_ih[65 + j] + b_hh[65 + j]);
        bhn[nbh] = make_float2(b_hh[128 + j], b_hh[129 + j]);
        bxn[nbh] = make_float2(b_ih[128 + j], b_ih[129 + j]);
    }

    float h[8];
#pragma unroll
    for (int i = 0; i < 8; ++i) h[i] = 0.0f;

    __syncthreads();   // x(t0) + A0 zero visible

    const int row0 = lane >> 2;
    const size_t xg_base = (size_t)(b0 + xrow) * 16 + xc2;

    for (int step = 0; step < TT; ++step) {
        const uint32_t pa = smb + ((step & 1) ? SM_A1 : SM_A0);
        char* const   pn = sm + ((step & 1) ? SM_A0 : SM_A1);

        // prefetch x(t+1)
        float2 xv;
        const bool do_x = (step + 1 < TT);
        if (do_x) {
            int tn = dir ? (TT - 2 - step) : (step + 1);
            xv = *(const float2*)(g_out1 + (size_t)tn * BATCH * 16 + xg_base);
        }

        // ---- A fragments (10 LDSM) ----
        uint32_t ah[4][4], al[4][4], axh[4], axl[4];
#pragma unroll
        for (int kc = 0; kc < 4; ++kc)
            LDSM_X4(ah[kc][0], ah[kc][1], ah[kc][2], ah[kc][3], pa + aRowOff + kc * 32);
#pragma unroll
        for (int kc = 0; kc < 4; ++kc)
            LDSM_X4(al[kc][0], al[kc][1], al[kc][2], al[kc][3], pa + aRowOff + 128 + kc * 32);
        LDSM_X4(axh[0], axh[1], axh[2], axh[3], pa + aRowOff + 256);
        LDSM_X4(axl[0], axl[1], axl[2], axl[3], pa + aRowOff + 288);

        // d accumulators initialized with biases:
        // d[0..1]=r, d[2..3]=z, d[4..5]=hn, d[6..7]=xn  (index = type*2 + nbh)
        float d[8][4];
#pragma unroll
        for (int nbh = 0; nbh < 2; ++nbh) {
            d[0 + nbh][0] = br[nbh].x;  d[0 + nbh][1] = br[nbh].y;
            d[0 + nbh][2] = br[nbh].x;  d[0 + nbh][3] = br[nbh].y;
            d[2 + nbh][0] = bz[nbh].x;  d[2 + nbh][1] = bz[nbh].y;
            d[2 + nbh][2] = bz[nbh].x;  d[2 + nbh][3] = bz[nbh].y;
            d[4 + nbh][0] = bhn[nbh].x; d[4 + nbh][1] = bhn[nbh].y;
            d[4 + nbh][2] = bhn[nbh].x; d[4 + nbh][3] = bhn[nbh].y;
            d[6 + nbh][0] = bxn[nbh].x; d[6 + nbh][1] = bxn[nbh].y;
            d[6 + nbh][2] = bxn[nbh].x; d[6 + nbh][3] = bxn[nbh].y;
        }

        // ---- MMA phase: 90 HMMA; Whh_hi from regs, Whh_lo/Wih from smem ----
#pragma unroll
        for (int sec = 0; sec < 3; ++sec) {
            const uint32_t rowb = (sec == 0) ? rowS0 : (sec == 1) ? rowS1 : rowS2;
            const int iH = (sec < 2) ? sec * 2 : 4;
            const int iX = (sec < 2) ? sec * 2 : 6;
            uint32_t q0, q1, q2, q3;
#pragma unroll
            for (int kc = 0; kc < 4; ++kc) {
                MMA_F16(d[iH],     ah[kc][0], ah[kc][1], ah[kc][2], ah[kc][3],
                        Bhh[sec][kc][0], Bhh[sec][kc][1]);
                MMA_F16(d[iH + 1], ah[kc][0], ah[kc][1], ah[kc][2], ah[kc][3],
                        Bhh[sec][kc][2], Bhh[sec][kc][3]);
                MMA_F16(d[iH],     al[kc][0], al[kc][1], al[kc][2], al[kc][3],
                        Bhh[sec][kc][0], Bhh[sec][kc][1]);
                MMA_F16(d[iH + 1], al[kc][0], al[kc][1], al[kc][2], al[kc][3],
                        Bhh[sec][kc][2], Bhh[sec][kc][3]);
                LDSM_X4(q0, q1, q2, q3, rowb + 128 + kc * 32);      // Whh_lo
                MMA_F16(d[iH],     ah[kc][0], ah[kc][1], ah[kc][2], ah[kc][3], q0, q1);
                MMA_F16(d[iH + 1], ah[kc][0], ah[kc][1], ah[kc][2], ah[kc][3], q2, q3);
            }
            LDSM_X4(q0, q1, q2, q3, rowb + 256);                    // Wih_hi
            MMA_F16(d[iX],     axh[0], axh[1], axh[2], axh[3], q0, q1);
            MMA_F16(d[iX + 1], axh[0], axh[1], axh[2], axh[3], q2, q3);
            MMA_F16(d[iX],     axl[0], axl[1], axl[2], axl[3], q0, q1);
            MMA_F16(d[iX + 1], axl[0], axl[1], axl[2], axl[3], q2, q3);
            LDSM_X4(q0, q1, q2, q3, rowb + 288);                    // Wih_lo
            MMA_F16(d[iX],     axh[0], axh[1], axh[2], axh[3], q0, q1);
            MMA_F16(d[iX + 1], axh[0], axh[1], axh[2], axh[3], q2, q3);
        }

        // No mid-step barrier (pn's previous readers finished before the
        // previous end-of-step barrier).

        // ---- epilogue (MUFU) + h writeback to next A buffer ----
#pragma unroll
        for (int nbh = 0; nbh < 2; ++nbh) {
#pragma unroll
            for (int e = 0; e < 4; ++e) {
                float rg = sig_mufu(d[0 + nbh][e]);
                float zg = sig_mufu(d[2 + nbh][e]);
                float nn = tanh_mufu(fmaf(rg, d[4 + nbh][e], d[6 + nbh][e]));
                const int hi = nbh * 4 + e;
                h[hi] = fmaf(zg, h[hi] - nn, nn);
            }
#pragma unroll
            for (int rsel = 0; rsel < 2; ++rsel) {
                const int e0 = rsel * 2;
                uint32_t LP, HP = f16_pair(h[nbh * 4 + e0], h[nbh * 4 + e0 + 1], LP);
                char* ar = pn + (row0 + rsel * 8) * AROW;
                const int j = jq * 16 + nbh * 8 + cj;
                *(uint32_t*)(ar + 2 * j)       = HP;   // h_hi
                *(uint32_t*)(ar + 128 + 2 * j) = LP;   // h_lo (col 64)
            }
        }

        // stage x(t+1)
        if (do_x) {
            uint32_t LP, HP = f16_pair(xv.x, xv.y, LP);
            char* ar = pn + xrow * AROW;
            *(uint32_t*)(ar + 256 + 2 * xc2) = HP;
            *(uint32_t*)(ar + 288 + 2 * xc2) = LP;
        }
        __syncthreads();   // A(next) complete before next step's LDSMs
    }

    // final hidden -> gmem
#pragma unroll
    for (int nbh = 0; nbh < 2; ++nbh) {
#pragma unroll
        for (int rsel = 0; rsel < 2; ++rsel) {
            const int j = jq * 16 + nbh * 8 + cj;
            float* hp = g_h + ((size_t)dir * BATCH + b0 + row0 + rsel * 8) * H2 + j;
            *(float2*)hp = make_float2(h[nbh * 4 + rsel * 2], h[nbh * 4 + rsel * 2 + 1]);
        }
    }
}

// ---------------------------------------------------------------------------
// Layer 1: GRU(2 -> 16), barrier-free warp-shuffle, MUFU activations.
// ---------------------------------------------------------------------------
__global__ void __launch_bounds__(256)
gru1_kernel(const float* __restrict__ traj,
            const float* __restrict__ w_ih1,
            const float* __restrict__ w_hh1,
            const float* __restrict__ b_ih1,
            const float* __restrict__ b_hh1) {
    const int tid  = threadIdx.x;
    const int wid  = tid >> 5;
    const int lane = tid & 31;
    const int half = lane >> 4;
    const int j    = lane & 15;
    const int el   = (blockIdx.x * 8 + wid) * 2 + half;

    float whr[16], whz[16], whn[16];
#pragma unroll
    for (int k = 0; k < 16; ++k) {
        whr[k] = w_hh1[(j)      * 16 + k];
        whz[k] = w_hh1[(16 + j) * 16 + k];
        whn[k] = w_hh1[(32 + j) * 16 + k];
    }
    const float wxr0 = w_ih1[j * 2 + 0],        wxr1 = w_ih1[j * 2 + 1];
    const float wxz0 = w_ih1[(16 + j) * 2 + 0], wxz1 = w_ih1[(16 + j) * 2 + 1];
    const float wxn0 = w_ih1[(32 + j) * 2 + 0], wxn1 = w_ih1[(32 + j) * 2 + 1];
    const float br  = b_ih1[j]      + b_hh1[j];
    const float bz  = b_ih1[16 + j] + b_hh1[16 + j];
    const float bxn = b_ih1[32 + j];
    const float bhn = b_hh1[32 + j];

    const float2* xp = (const float2*)(traj + (size_t)el * TT * 2);
    float* op = g_out1 + (size_t)el * 16 + j;
    const int sbase = half << 4;

    float h = 0.0f;
    float2 xv = xp[0];
    for (int t = 0; t < TT; ++t) {
        float x0 = xv.x, x1 = xv.y;
        if (t + 1 < TT) xv = xp[t + 1];

        float ar  = fmaf(wxr1, x1, fmaf(wxr0, x0, br));
        float az  = fmaf(wxz1, x1, fmaf(wxz0, x0, bz));
        float axn = fmaf(wxn1, x1, fmaf(wxn0, x0, bxn));
        float ahn = bhn;
#pragma unroll
        for (int k = 0; k < 16; ++k) {
            float hk = __shfl_sync(0xFFFFFFFFu, h, sbase + k);
            ar  = fmaf(whr[k], hk, ar);
            az  = fmaf(whz[k], hk, az);
            ahn = fmaf(whn[k], hk, ahn);
        }
        float r = sig_mufu(ar);
        float z = sig_mufu(az);
        float n = tanh_mufu(fmaf(r, ahn, axn));
        h = fmaf(z, h - n, n);
        op[(size_t)t * BATCH * 16] = h;
    }
}

// ---------------------------------------------------------------------------
// MLP
// ---------------------------------------------------------------------------
__global__ void mlp_kernel(const float* __restrict__ W1, const float* __restrict__ b1,
                           const float* __restrict__ W2, const float* __restrict__ b2,
                           float* __restrict__ out) {
    __shared__ float s_w1t[64 * 32];
    __shared__ float s_w2t[32 * 8];
    __shared__ float s_b1[32];
    __shared__ float s_b2[8];
    __shared__ float s_m1[8 * 32];

    const int tid = threadIdx.x;
    for (int idx = tid; idx < 32 * 64; idx += 256) {
        int mm = idx >> 6, k = idx & 63;
        s_w1t[k * 32 + mm] = W1[idx];
    }
    if (tid < 8 * 32) { int o = tid >> 5, k = tid & 31; s_w2t[k * 8 + o] = W2[tid]; }
    if (tid < 32) s_b1[tid] = b1[tid];
    if (tid < 8)  s_b2[tid] = b2[tid];
    __syncthreads();

    const int bl = tid >> 5;
    const int mm = tid & 31;
    const int gb = blockIdx.x * 8 + bl;

    const float* hf = g_h + (size_t)gb * H2;
    const float* hb = g_h + (size_t)(BATCH + gb) * H2;

    float acc = s_b1[mm];
#pragma unroll
    for (int k = 0; k < 64; ++k)
        acc = fmaf(s_w1t[k * 32 + mm], hf[k] + hb[k], acc);
    s_m1[bl * 32 + mm] = acc;
    __syncthreads();

    if (mm < 8) {
        float a2 = s_b2[mm];
#pragma unroll
        for (int k = 0; k < 32; ++k)
            a2 = fmaf(s_w2t[k * 8 + mm], s_m1[bl * 32 + k], a2);
        out[(size_t)gb * 8 + mm] = a2;
    }
}

// ---------------------------------------------------------------------------
// Launch
// ---------------------------------------------------------------------------
extern "C" void kernel_launch(void* const* d_in, const int* in_sizes, int n_in,
                              void* d_out, int out_size) {
    const float* traj   = (const float*)d_in[0];
    const float* w_ih1  = (const float*)d_in[1];
    const float* w_hh1  = (const float*)d_in[2];
    const float* b_ih1  = (const float*)d_in[3];
    const float* b_hh1  = (const float*)d_in[4];
    const float* w_ih2f = (const float*)d_in[5];
    const float* w_hh2f = (const float*)d_in[6];
    const float* b_ih2f = (const float*)d_in[7];
    const float* b_hh2f = (const float*)d_in[8];
    const float* w_ih2b = (const float*)d_in[9];
    const float* w_hh2b = (const float*)d_in[10];
    const float* b_ih2b = (const float*)d_in[11];
    const float* b_hh2b = (const float*)d_in[12];
    const float* W1     = (const float*)d_in[13];
    const float* b1     = (const float*)d_in[14];
    const float* W2     = (const float*)d_in[15];
    const float* b2     = (const float*)d_in[16];

    cudaFuncSetAttribute(gru2_kernel,
                         cudaFuncAttributeMaxDynamicSharedMemorySize, SM2_TOTAL);

    gru1_kernel<<<BATCH / 16, 256>>>(traj, w_ih1, w_hh1, b_ih1, b_hh1);

    dim3 grid2(BATCH / 16, 2);   // (256, 2) = 512 CTAs @ 3/SM -> 1.15 waves
    gru2_kernel<<<grid2, 128, SM2_TOTAL>>>(w_ih2f, w_hh2f, b_ih2f, b_hh2f,
                                           w_ih2b, w_hh2b, b_ih2b, b_hh2b);

    mlp_kernel<<<BATCH / 8, 256>>>(W1, b1, W2, b2, (float*)d_out);
}

// round 17
// speedup vs baseline: 1.1739x; 1.1739x over previous
#include <cuda_runtime.h>
#include <cuda_fp16.h>
#include <cstdint>

#define TT    256
#define BATCH 4096
#define H1    16
#define H2    64

// ---------------------------------------------------------------------------
// Scratch
// ---------------------------------------------------------------------------
__device__ float g_out1[(size_t)TT * BATCH * H1];   // layer-1 outputs [T][B][16]
__device__ float g_h[2 * (size_t)BATCH * H2];       // final hidden per dir

// ---------------------------------------------------------------------------
// MUFU activations (EX2+RCP)
// ---------------------------------------------------------------------------
__device__ __forceinline__ float sig_mufu(float x) {
    return __fdividef(1.0f, 1.0f + __expf(-x));
}
__device__ __forceinline__ float tanh_mufu(float x) {
    return fmaf(2.0f, __fdividef(1.0f, 1.0f + __expf(-2.0f * x)), -1.0f);
}

__device__ __forceinline__ uint32_t smem_u32(const void* p) {
    uint32_t a;
    asm("{ .reg .u64 t; cvta.to.shared.u64 t, %1; cvt.u32.u64 %0, t; }" : "=r"(a) : "l"(p));
    return a;
}

#define LDSM_X4(r0, r1, r2, r3, addr) \
    asm volatile("ldmatrix.sync.aligned.m8n8.x4.shared.b16 {%0,%1,%2,%3}, [%4];" \
        : "=r"(r0), "=r"(r1), "=r"(r2), "=r"(r3) : "r"(addr))

#define MMA_F16(d, a0, a1, a2, a3, bb0, bb1) \
    asm volatile("mma.sync.aligned.m16n8k16.row.col.f32.f16.f16.f32 " \
        "{%0,%1,%2,%3}, {%4,%5,%6,%7}, {%8,%9}, {%0,%1,%2,%3};" \
        : "+f"((d)[0]), "+f"((d)[1]), "+f"((d)[2]), "+f"((d)[3]) \
        : "r"(a0), "r"(a1), "r"(a2), "r"(a3), "r"(bb0), "r"(bb1))

// fp16 split: v = hi + lo
__device__ __forceinline__ void f16_split(float v, unsigned short& hi, unsigned short& lo) {
    __half h = __float2half_rn(v);
    float rem = v - __half2float(h);
    __half l = __float2half_rn(rem);
    hi = __half_as_ushort(h);
    lo = __half_as_ushort(l);
}
__device__ __forceinline__ uint32_t f16_pair(float a, float b, uint32_t& lop) {
    unsigned short ha, la, hb, lb;
    f16_split(a, ha, la);
    f16_split(b, hb, lb);
    lop = (uint32_t)la | ((uint32_t)lb << 16);
    return (uint32_t)ha | ((uint32_t)hb << 16);
}

// ---------------------------------------------------------------------------
// Layer 2 (HMMA, fp16 3-term split): TWO independent 16-row tiles per CTA.
//   - grid (128, 2) = 256 CTAs @ 2/SM -> ONE clean wave (R15's 512 CTAs ran
//     1.73 ragged waves and wasted its halved per-step time).
//   - each B fragment LDSM feeds 4 MMAs (both tiles) -> 30 B-LDSM/step-pair.
//   - epilogue(t0) (MUFU) issues while MMA(t1) drains the tensor pipe:
//     in-warp cross-tile overlap, independent of barriers/occupancy.
//   A: [0:64) h_hi | [64:128) h_lo | [128:144) x_hi | [144:160) x_lo
//   B: [0:64) Whh_hi | [64:128) Whh_lo | [128:144) Wih_hi | [144:160) Wih_lo
// CTA = 128 threads = 4 warps; warp jq owns gates [jq*16,+16) for BOTH tiles.
// ---------------------------------------------------------------------------
#define AROW   336
#define SM_A00 0                     // tile0 buf0
#define SM_A01 5376                  // tile0 buf1
#define SM_A10 10752                 // tile1 buf0
#define SM_A11 16128                 // tile1 buf1
#define SM_B   21504
#define SM2_TOTAL (21504 + 192 * 336)    // 86016 (x2 CTAs = 172 KB)

__global__ void __launch_bounds__(128, 2)
gru2_kernel(const float* __restrict__ w_ihf, const float* __restrict__ w_hhf,
            const float* __restrict__ b_ihf, const float* __restrict__ b_hhf,
            const float* __restrict__ w_ihb, const float* __restrict__ w_hhb,
            const float* __restrict__ b_ihb, const float* __restrict__ b_hhb) {
    extern __shared__ char sm[];
    const uint32_t smb = smem_u32(sm);
    const int tid = threadIdx.x;
    const int wid = tid >> 5;
    const int lane = tid & 31;
    const int dir = blockIdx.y;
    const int b0 = blockIdx.x * 32;      // tile0: rows b0.., tile1: rows b0+16..

    const float* w_ih = dir ? w_ihb : w_ihf;
    const float* w_hh = dir ? w_hhb : w_hhf;
    const float* b_ih = dir ? b_ihb : b_ihf;
    const float* b_hh = dir ? b_hhb : b_hhf;

    // ---- build B in smem ----
    for (int idx = tid; idx < 192 * 64; idx += 128) {
        int g = idx >> 6, k = idx & 63;
        unsigned short hi, lo;
        f16_split(w_hh[idx], hi, lo);
        unsigned short* row = (unsigned short*)(sm + SM_B + g * AROW);
        row[k] = hi; row[64 + k] = lo;
    }
    for (int idx = tid; idx < 192 * 16; idx += 128) {
        int g = idx >> 4, k = idx & 15;
        unsigned short hi, lo;
        f16_split(w_ih[idx], hi, lo);
        unsigned short* row = (unsigned short*)(sm + SM_B + g * AROW);
        row[128 + k] = hi; row[144 + k] = lo;
    }
    for (int g = tid; g < 192; g += 128)
        *(uint4*)(sm + SM_B + g * AROW + 320) = make_uint4(0, 0, 0, 0);

    // ---- zero A buf0 of both tiles (h(0)=0) ----
    for (int idx = tid; idx < 16 * (AROW / 16); idx += 128) {
        ((uint4*)(sm + SM_A00))[idx] = make_uint4(0, 0, 0, 0);
        ((uint4*)(sm + SM_A10))[idx] = make_uint4(0, 0, 0, 0);
    }
    __syncthreads();

    // ---- stage x(t0) for both tiles: 128 threads = 16 rows x 8 col-pairs ----
    const int xrow = tid >> 3;          // 0..15
    const int xc2  = (tid & 7) * 2;     // 0,2,...,14
    {
        int t0 = dir ? (TT - 1) : 0;
        float2 xa = *(const float2*)(g_out1 + ((size_t)t0 * BATCH + b0 + xrow) * 16 + xc2);
        float2 xb = *(const float2*)(g_out1 + ((size_t)t0 * BATCH + b0 + 16 + xrow) * 16 + xc2);
        uint32_t LPa, HPa = f16_pair(xa.x, xa.y, LPa);
        uint32_t LPb, HPb = f16_pair(xb.x, xb.y, LPb);
        char* ar0 = sm + SM_A00 + xrow * AROW;
        char* ar1 = sm + SM_A10 + xrow * AROW;
        *(uint32_t*)(ar0 + 256 + 2 * xc2) = HPa;
        *(uint32_t*)(ar0 + 288 + 2 * xc2) = LPa;
        *(uint32_t*)(ar1 + 256 + 2 * xc2) = HPb;
        *(uint32_t*)(ar1 + 288 + 2 * xc2) = LPb;
    }

    // ---- per-warp / per-lane constants ----
    const int jq = wid;                 // gate slice [jq*16, jq*16+16)
    const int lrow = lane & 7;
    const int grp  = lane >> 3;
    const uint32_t aRowOff = (uint32_t)(lrow + ((grp & 1) << 3)) * AROW
                           + (uint32_t)((grp >> 1) << 4);
    const uint32_t bOff = (uint32_t)(lrow + ((grp >> 1) << 3)) * AROW
                        + (uint32_t)((grp & 1) << 4);
    const uint32_t rowS0 = smb + SM_B + bOff + (uint32_t)(jq * 16) * AROW;
    const uint32_t rowS1 = rowS0 + (uint32_t)64 * AROW;
    const uint32_t rowS2 = rowS0 + (uint32_t)128 * AROW;

    // biases (d-accumulator init values)
    const int cj = 2 * (lane & 3);
    float2 br[2], bz[2], bhn[2], bxn[2];
#pragma unroll
    for (int nbh = 0; nbh < 2; ++nbh) {
        int j = jq * 16 + nbh * 8 + cj;
        br[nbh]  = make_float2(b_ih[j] + b_hh[j],           b_ih[j + 1] + b_hh[j + 1]);
        bz[nbh]  = make_float2(b_ih[64 + j] + b_hh[64 + j], b_ih[65 + j] + b_hh[65 + j]);
        bhn[nbh] = make_float2(b_hh[128 + j], b_hh[129 + j]);
        bxn[nbh] = make_float2(b_ih[128 + j], b_ih[129 + j]);
    }

    float h0[8], h1[8];
#pragma unroll
    for (int i = 0; i < 8; ++i) { h0[i] = 0.0f; h1[i] = 0.0f; }

    __syncthreads();   // x(t0) + A0 zero visible

    const int row0 = lane >> 2;
    const size_t xg0 = (size_t)(b0 + xrow) * 16 + xc2;
    const size_t xg1 = (size_t)(b0 + 16 + xrow) * 16 + xc2;

    for (int step = 0; step < TT; ++step) {
        const int bufsel = step & 1;
        const uint32_t pa0 = smb + (bufsel ? SM_A01 : SM_A00);
        const uint32_t pa1 = smb + (bufsel ? SM_A11 : SM_A10);
        char* const   pn0 = sm + (bufsel ? SM_A00 : SM_A01);
        char* const   pn1 = sm + (bufsel ? SM_A10 : SM_A11);

        // prefetch x(t+1) for both tiles
        float2 xva, xvb;
        const bool do_x = (step + 1 < TT);
        if (do_x) {
            int tn = dir ? (TT - 2 - step) : (step + 1);
            xva = *(const float2*)(g_out1 + (size_t)tn * BATCH * 16 + xg0);
            xvb = *(const float2*)(g_out1 + (size_t)tn * BATCH * 16 + xg1);
        }

        // ---- A fragments for both tiles (20 LDSM) ----
        uint32_t ah0[4][4], al0[4][4], axh0[4], axl0[4];
        uint32_t ah1[4][4], al1[4][4], axh1[4], axl1[4];
#pragma unroll
        for (int kc = 0; kc < 4; ++kc) {
            LDSM_X4(ah0[kc][0], ah0[kc][1], ah0[kc][2], ah0[kc][3], pa0 + aRowOff + kc * 32);
            LDSM_X4(ah1[kc][0], ah1[kc][1], ah1[kc][2], ah1[kc][3], pa1 + aRowOff + kc * 32);
        }
#pragma unroll
        for (int kc = 0; kc < 4; ++kc) {
            LDSM_X4(al0[kc][0], al0[kc][1], al0[kc][2], al0[kc][3], pa0 + aRowOff + 128 + kc * 32);
            LDSM_X4(al1[kc][0], al1[kc][1], al1[kc][2], al1[kc][3], pa1 + aRowOff + 128 + kc * 32);
        }
        LDSM_X4(axh0[0], axh0[1], axh0[2], axh0[3], pa0 + aRowOff + 256);
        LDSM_X4(axl0[0], axl0[1], axl0[2], axl0[3], pa0 + aRowOff + 288);
        LDSM_X4(axh1[0], axh1[1], axh1[2], axh1[3], pa1 + aRowOff + 256);
        LDSM_X4(axl1[0], axl1[1], axl1[2], axl1[3], pa1 + aRowOff + 288);

        // d accumulators (biases pre-loaded): index = type*2 + nbh
        float d0[8][4], d1[8][4];
#pragma unroll
        for (int nbh = 0; nbh < 2; ++nbh) {
#pragma unroll
            for (int e = 0; e < 4; ++e) {
                float vr = (e & 1) ? br[nbh].y : br[nbh].x;
                float vz = (e & 1) ? bz[nbh].y : bz[nbh].x;
                float vh = (e & 1) ? bhn[nbh].y : bhn[nbh].x;
                float vx = (e & 1) ? bxn[nbh].y : bxn[nbh].x;
                d0[0 + nbh][e] = vr; d1[0 + nbh][e] = vr;
                d0[2 + nbh][e] = vz; d1[2 + nbh][e] = vz;
                d0[4 + nbh][e] = vh; d1[4 + nbh][e] = vh;
                d0[6 + nbh][e] = vx; d1[6 + nbh][e] = vx;
            }
        }

        // ---- MMA phase: 180 HMMA; each B fragment feeds BOTH tiles ----
#pragma unroll
        for (int sec = 0; sec < 3; ++sec) {
            const uint32_t rowb = (sec == 0) ? rowS0 : (sec == 1) ? rowS1 : rowS2;
            const int iH = (sec < 2) ? sec * 2 : 4;
            const int iX = (sec < 2) ? sec * 2 : 6;
            uint32_t q0, q1, q2, q3;
#pragma unroll
            for (int kc = 0; kc < 4; ++kc) {
                LDSM_X4(q0, q1, q2, q3, rowb + kc * 32);            // Whh_hi
                MMA_F16(d0[iH],     ah0[kc][0], ah0[kc][1], ah0[kc][2], ah0[kc][3], q0, q1);
                MMA_F16(d0[iH + 1], ah0[kc][0], ah0[kc][1], ah0[kc][2], ah0[kc][3], q2, q3);
                MMA_F16(d1[iH],     ah1[kc][0], ah1[kc][1], ah1[kc][2], ah1[kc][3], q0, q1);
                MMA_F16(d1[iH + 1], ah1[kc][0], ah1[kc][1], ah1[kc][2], ah1[kc][3], q2, q3);
                MMA_F16(d0[iH],     al0[kc][0], al0[kc][1], al0[kc][2], al0[kc][3], q0, q1);
                MMA_F16(d0[iH + 1], al0[kc][0], al0[kc][1], al0[kc][2], al0[kc][3], q2, q3);
                MMA_F16(d1[iH],     al1[kc][0], al1[kc][1], al1[kc][2], al1[kc][3], q0, q1);
                MMA_F16(d1[iH + 1], al1[kc][0], al1[kc][1], al1[kc][2], al1[kc][3], q2, q3);
                LDSM_X4(q0, q1, q2, q3, rowb + 128 + kc * 32);      // Whh_lo
                MMA_F16(d0[iH],     ah0[kc][0], ah0[kc][1], ah0[kc][2], ah0[kc][3], q0, q1);
                MMA_F16(d0[iH + 1], ah0[kc][0], ah0[kc][1], ah0[kc][2], ah0[kc][3], q2, q3);
                MMA_F16(d1[iH],     ah1[kc][0], ah1[kc][1], ah1[kc][2], ah1[kc][3], q0, q1);
                MMA_F16(d1[iH + 1], ah1[kc][0], ah1[kc][1], ah1[kc][2], ah1[kc][3], q2, q3);
            }
            LDSM_X4(q0, q1, q2, q3, rowb + 256);                    // Wih_hi
            MMA_F16(d0[iX],     axh0[0], axh0[1], axh0[2], axh0[3], q0, q1);
            MMA_F16(d0[iX + 1], axh0[0], axh0[1], axh0[2], axh0[3], q2, q3);
            MMA_F16(d1[iX],     axh1[0], axh1[1], axh1[2], axh1[3], q0, q1);
            MMA_F16(d1[iX + 1], axh1[0], axh1[1], axh1[2], axh1[3], q2, q3);
            MMA_F16(d0[iX],     axl0[0], axl0[1], axl0[2], axl0[3], q0, q1);
            MMA_F16(d0[iX + 1], axl0[0], axl0[1], axl0[2], axl0[3], q2, q3);
            MMA_F16(d1[iX],     axl1[0], axl1[1], axl1[2], axl1[3], q0, q1);
            MMA_F16(d1[iX + 1], axl1[0], axl1[1], axl1[2], axl1[3], q2, q3);
            LDSM_X4(q0, q1, q2, q3, rowb + 288);                    // Wih_lo
            MMA_F16(d0[iX],     axh0[0], axh0[1], axh0[2], axh0[3], q0, q1);
            MMA_F16(d0[iX + 1], axh0[0], axh0[1], axh0[2], axh0[3], q2, q3);
            MMA_F16(d1[iX],     axh1[0], axh1[1], axh1[2], axh1[3], q0, q1);
            MMA_F16(d1[iX + 1], axh1[0], axh1[1], axh1[2], axh1[3], q2, q3);
        }

        // ---- epilogue tile0 (MUFU; issues while tile1's MMAs drain) ----
#pragma unroll
        for (int nbh = 0; nbh < 2; ++nbh) {
#pragma unroll
            for (int e = 0; e < 4; ++e) {
                float rg = sig_mufu(d0[0 + nbh][e]);
                float zg = sig_mufu(d0[2 + nbh][e]);
                float nn = tanh_mufu(fmaf(rg, d0[4 + nbh][e], d0[6 + nbh][e]));
                const int hi = nbh * 4 + e;
                h0[hi] = fmaf(zg, h0[hi] - nn, nn);
            }
#pragma unroll
            for (int rsel = 0; rsel < 2; ++rsel) {
                const int e0 = rsel * 2;
                uint32_t LP, HP = f16_pair(h0[nbh * 4 + e0], h0[nbh * 4 + e0 + 1], LP);
                char* ar = pn0 + (row0 + rsel * 8) * AROW;
                const int j = jq * 16 + nbh * 8 + cj;
                *(uint32_t*)(ar + 2 * j)       = HP;
                *(uint32_t*)(ar + 128 + 2 * j) = LP;
            }
        }
        // ---- epilogue tile1 ----
#pragma unroll
        for (int nbh = 0; nbh < 2; ++nbh) {
#pragma unroll
            for (int e = 0; e < 4; ++e) {
                float rg = sig_mufu(d1[0 + nbh][e]);
                float zg = sig_mufu(d1[2 + nbh][e]);
                float nn = tanh_mufu(fmaf(rg, d1[4 + nbh][e], d1[6 + nbh][e]));
                const int hi = nbh * 4 + e;
                h1[hi] = fmaf(zg, h1[hi] - nn, nn);
            }
#pragma unroll
            for (int rsel = 0; rsel < 2; ++rsel) {
                const int e0 = rsel * 2;
                uint32_t LP, HP = f16_pair(h1[nbh * 4 + e0], h1[nbh * 4 + e0 + 1], LP);
                char* ar = pn1 + (row0 + rsel * 8) * AROW;
                const int j = jq * 16 + nbh * 8 + cj;
                *(uint32_t*)(ar + 2 * j)       = HP;
                *(uint32_t*)(ar + 128 + 2 * j) = LP;
            }
        }

        // stage x(t+1) for both tiles
        if (do_x) {
            uint32_t LPa, HPa = f16_pair(xva.x, xva.y, LPa);
            uint32_t LPb, HPb = f16_pair(xvb.x, xvb.y, LPb);
            char* ar0 = pn0 + xrow * AROW;
            char* ar1 = pn1 + xrow * AROW;
            *(uint32_t*)(ar0 + 256 + 2 * xc2) = HPa;
            *(uint32_t*)(ar0 + 288 + 2 * xc2) = LPa;
            *(uint32_t*)(ar1 + 256 + 2 * xc2) = HPb;
            *(uint32_t*)(ar1 + 288 + 2 * xc2) = LPb;
        }
        __syncthreads();   // next-step A buffers complete before next LDSMs
    }

    // final hidden -> gmem (both tiles)
#pragma unroll
    for (int nbh = 0; nbh < 2; ++nbh) {
#pragma unroll
        for (int rsel = 0; rsel < 2; ++rsel) {
            const int j = jq * 16 + nbh * 8 + cj;
            float* hp0 = g_h + ((size_t)dir * BATCH + b0 + row0 + rsel * 8) * H2 + j;
            float* hp1 = g_h + ((size_t)dir * BATCH + b0 + 16 + row0 + rsel * 8) * H2 + j;
            *(float2*)hp0 = make_float2(h0[nbh * 4 + rsel * 2], h0[nbh * 4 + rsel * 2 + 1]);
            *(float2*)hp1 = make_float2(h1[nbh * 4 + rsel * 2], h1[nbh * 4 + rsel * 2 + 1]);
        }
    }
}

// ---------------------------------------------------------------------------
// Layer 1: GRU(2 -> 16), barrier-free warp-shuffle, MUFU activations.
// ---------------------------------------------------------------------------
__global__ void __launch_bounds__(256)
gru1_kernel(const float* __restrict__ traj,
            const float* __restrict__ w_ih1,
            const float* __restrict__ w_hh1,
            const float* __restrict__ b_ih1,
            const float* __restrict__ b_hh1) {
    const int tid  = threadIdx.x;
    const int wid  = tid >> 5;
    const int lane = tid & 31;
    const int half = lane >> 4;
    const int j    = lane & 15;
    const int el   = (blockIdx.x * 8 + wid) * 2 + half;

    float whr[16], whz[16], whn[16];
#pragma unroll
    for (int k = 0; k < 16; ++k) {
        whr[k] = w_hh1[(j)      * 16 + k];
        whz[k] = w_hh1[(16 + j) * 16 + k];
        whn[k] = w_hh1[(32 + j) * 16 + k];
    }
    const float wxr0 = w_ih1[j * 2 + 0],        wxr1 = w_ih1[j * 2 + 1];
    const float wxz0 = w_ih1[(16 + j) * 2 + 0], wxz1 = w_ih1[(16 + j) * 2 + 1];
    const float wxn0 = w_ih1[(32 + j) * 2 + 0], wxn1 = w_ih1[(32 + j) * 2 + 1];
    const float br  = b_ih1[j]      + b_hh1[j];
    const float bz  = b_ih1[16 + j] + b_hh1[16 + j];
    const float bxn = b_ih1[32 + j];
    const float bhn = b_hh1[32 + j];

    const float2* xp = (const float2*)(traj + (size_t)el * TT * 2);
    float* op = g_out1 + (size_t)el * 16 + j;
    const int sbase = half << 4;

    float h = 0.0f;
    float2 xv = xp[0];
    for (int t = 0; t < TT; ++t) {
        float x0 = xv.x, x1 = xv.y;
        if (t + 1 < TT) xv = xp[t + 1];

        float ar  = fmaf(wxr1, x1, fmaf(wxr0, x0, br));
        float az  = fmaf(wxz1, x1, fmaf(wxz0, x0, bz));
        float axn = fmaf(wxn1, x1, fmaf(wxn0, x0, bxn));
        float ahn = bhn;
#pragma unroll
        for (int k = 0; k < 16; ++k) {
            float hk = __shfl_sync(0xFFFFFFFFu, h, sbase + k);
            ar  = fmaf(whr[k], hk, ar);
            az  = fmaf(whz[k], hk, az);
            ahn = fmaf(whn[k], hk, ahn);
        }
        float r = sig_mufu(ar);
        float z = sig_mufu(az);
        float n = tanh_mufu(fmaf(r, ahn, axn));
        h = fmaf(z, h - n, n);
        op[(size_t)t * BATCH * 16] = h;
    }
}

// ---------------------------------------------------------------------------
// MLP
// ---------------------------------------------------------------------------
__global__ void mlp_kernel(const float* __restrict__ W1, const float* __restrict__ b1,
                           const float* __restrict__ W2, const float* __restrict__ b2,
                           float* __restrict__ out) {
    __shared__ float s_w1t[64 * 32];
    __shared__ float s_w2t[32 * 8];
    __shared__ float s_b1[32];
    __shared__ float s_b2[8];
    __shared__ float s_m1[8 * 32];

    const int tid = threadIdx.x;
    for (int idx = tid; idx < 32 * 64; idx += 256) {
        int mm = idx >> 6, k = idx & 63;
        s_w1t[k * 32 + mm] = W1[idx];
    }
    if (tid < 8 * 32) { int o = tid >> 5, k = tid & 31; s_w2t[k * 8 + o] = W2[tid]; }
    if (tid < 32) s_b1[tid] = b1[tid];
    if (tid < 8)  s_b2[tid] = b2[tid];
    __syncthreads();

    const int bl = tid >> 5;
    const int mm = tid & 31;
    const int gb = blockIdx.x * 8 + bl;

    const float* hf = g_h + (size_t)gb * H2;
    const float* hb = g_h + (size_t)(BATCH + gb) * H2;

    float acc = s_b1[mm];
#pragma unroll
    for (int k = 0; k < 64; ++k)
        acc = fmaf(s_w1t[k * 32 + mm], hf[k] + hb[k], acc);
    s_m1[bl * 32 + mm] = acc;
    __syncthreads();

    if (mm < 8) {
        float a2 = s_b2[mm];
#pragma unroll
        for (int k = 0; k < 32; ++k)
            a2 = fmaf(s_w2t[k * 8 + mm], s_m1[bl * 32 + k], a2);
        out[(size_t)gb * 8 + mm] = a2;
    }
}

// ---------------------------------------------------------------------------
// Launch
// ---------------------------------------------------------------------------
extern "C" void kernel_launch(void* const* d_in, const int* in_sizes, int n_in,
                              void* d_out, int out_size) {
    const float* traj   = (const float*)d_in[0];
    const float* w_ih1  = (const float*)d_in[1];
    const float* w_hh1  = (const float*)d_in[2];
    const float* b_ih1  = (const float*)d_in[3];
    const float* b_hh1  = (const float*)d_in[4];
    const float* w_ih2f = (const float*)d_in[5];
    const float* w_hh2f = (const float*)d_in[6];
    const float* b_ih2f = (const float*)d_in[7];
    const float* b_hh2f = (const float*)d_in[8];
    const float* w_ih2b = (const float*)d_in[9];
    const float* w_hh2b = (const float*)d_in[10];
    const float* b_ih2b = (const float*)d_in[11];
    const float* b_hh2b = (const float*)d_in[12];
    const float* W1     = (const float*)d_in[13];
    const float* b1     = (const float*)d_in[14];
    const float* W2     = (const float*)d_in[15];
    const float* b2     = (const float*)d_in[16];

    cudaFuncSetAttribute(gru2_kernel,
                         cudaFuncAttributeMaxDynamicSharedMemorySize, SM2_TOTAL);

    gru1_kernel<<<BATCH / 16, 256>>>(traj, w_ih1, w_hh1, b_ih1, b_hh1);

    dim3 grid2(BATCH / 32, 2);   // (128, 2) = 256 CTAs @ 2/SM -> ONE wave
    gru2_kernel<<<grid2, 128, SM2_TOTAL>>>(w_ih2f, w_hh2f, b_ih2f, b_hh2f,
                                           w_ih2b, w_hh2b, b_ih2b, b_hh2b);

    mlp_kernel<<<BATCH / 8, 256>>>(W1, b1, W2, b2, (float*)d_out);
}